// round 5
// baseline (speedup 1.0000x reference)
#include <cuda_runtime.h>
#include <cstdint>

#define BB 128          // batch
#define PP 1200         // feature dim
#define NPB (BB * PP)   // 153600
#define MAXCH 12        // max p-chunks per iteration

// Static scratch (no allocations allowed)
__device__ float g_h[NPB];               // h state (in-place updated)
__device__ float g_C[NPB];               // frozen-contribution cache C[b,q]
__device__ float g_partial[MAXCH * NPB]; // per-chunk partial sums [chunk][b][q]

__device__ __forceinline__ float f_p(float x) {
    float t = fminf(fmaxf(x, -1.0f), 1.0f);
    return t > 0.0f ? t : 0.01f * t;
}

// 16-byte streaming load as two packed f32x2 (64-bit) registers
struct U64x2 { unsigned long long a, b; };
__device__ __forceinline__ U64x2 ldg_cs_128(const void* p) {
    U64x2 r;
    asm("ld.global.cs.v2.u64 {%0,%1}, [%2];" : "=l"(r.a), "=l"(r.b) : "l"(p));
    return r;
}

// Packed dual-fp32 FMA: acc = m * hp + acc   (Blackwell f32x2 pipe)
#define FMA2(acc, m, hp) \
    asm("fma.rn.f32x2 %0, %1, %2, %0;" : "+l"(acc) : "l"(m), "l"(hp))

// ---------------------------------------------------------------------------
// phase A: partial[ch][b][q] = sum_{p in chunk} h[b,p] * M[b,p,q]
// Grid: (nchunks, B, qtiles). Thread owns 4 consecutive q -> every warp
// LDG.128 is a contiguous request. PC compile-time (static trip count).
// IT0: h comes from f_p(query) directly (no init kernel needed).
// ---------------------------------------------------------------------------
template<int PC, bool IT0>
__global__ void phaseA(const float* __restrict__ M,
                       const float* __restrict__ hsrc, int n_on)
{
    const int ch  = blockIdx.x;
    const int b   = blockIdx.y;
    const int tid = threadIdx.x;
    const int pbase = ch * PC;

    __shared__ float2 hd[PC];
    #pragma unroll
    for (int i = tid; i < PC; i += blockDim.x) {
        float v = hsrc[b * PP + pbase + i];
        if (IT0) v = f_p(v);
        hd[i] = make_float2(v, v);
    }
    __syncthreads();

    const int q0 = blockIdx.z * (blockDim.x * 4) + tid * 4;
    if (q0 >= n_on) return;

    const char* base = (const char*)(M + (size_t)b * PP * PP
                                       + (size_t)pbase * PP + q0);

    unsigned long long acc0 = 0, acc1 = 0;

    #pragma unroll 8
    for (int p = 0; p < PC; ++p) {
        unsigned long long hp = *reinterpret_cast<const unsigned long long*>(&hd[p]);
        U64x2 m = ldg_cs_128(base + (size_t)p * (PP * 4));
        FMA2(acc0, m.a, hp);
        FMA2(acc1, m.b, hp);
    }

    unsigned long long* out = reinterpret_cast<unsigned long long*>(
        g_partial + ((size_t)ch * BB + b) * PP + q0);
    out[0] = acc0;
    out[1] = acc1;
}

// ---------------------------------------------------------------------------
// phase B (fully templated per iteration):
//   mv = [C] + sum(partials); h = f_p(h*(kappa+mv)) in place (q < NON);
//   fold newly-frozen chunk contributions into C (first fold writes, not adds).
//   Last iteration writes d_out (full range incl. frozen passthrough).
// ---------------------------------------------------------------------------
template<int NON, int NCH, int NACT, bool READC, bool WRITEC, bool FIRSTW,
         bool IT0, bool LAST>
__global__ void phaseB_k(float* __restrict__ out, const float* __restrict__ query)
{
    int i = blockIdx.x * blockDim.x + threadIdx.x;

    int b, q, gi;
    if (LAST) {
        if (i >= NPB) return;
        b = i / PP; q = i % PP; gi = i;
        if (q >= NON) { out[gi] = g_h[gi]; return; }
    } else {
        if (i >= BB * NON) return;
        b = i / NON; q = i % NON; gi = b * PP + q;
    }

    float h = IT0 ? f_p(query[gi]) : g_h[gi];

    float sa = 0.0f, sf = 0.0f;
    const float* pp = g_partial + (size_t)b * PP + q;
    #pragma unroll
    for (int s = 0; s < NCH; ++s) {
        float v = pp[(size_t)s * NPB];
        if (s < NACT) sa += v; else sf += v;
    }

    float c  = READC ? g_C[gi] : 0.0f;
    float mv = sa + sf + c;
    if (WRITEC) g_C[gi] = FIRSTW ? sf : (c + sf);

    float val = f_p(h * (0.8f + mv));
    if (LAST) out[gi] = val; else g_h[gi] = val;
}

// ---------------------------------------------------------------------------
extern "C" void kernel_launch(void* const* d_in, const int* in_sizes, int n_in,
                              void* d_out, int out_size)
{
    const float* query = (const float*)d_in[0];
    const float* M     = (const float*)d_in[1];
    float*       out   = (float*)d_out;

    float* hbase;
    cudaGetSymbolAddress((void**)&hbase, g_h);

    // Iteration plan (prev = p-range read, non = active q/p range):
    //  it : prev  non  pc  nch nact bd qtiles  grid
    //  0  : 1200 1200 120  10  10  128   3    3840
    //  1  : 1200  960 120  10   8  128   2    2560
    //  2  :  960  720 120   8   6  128   2    2048
    //  3  :  720  480  60  12   8  128   1    1536
    //  4  :  480  240  60   8   4   64   1    1024

    // --- iter 0 ---
    phaseA<120, true ><<<dim3(10, BB, 3), 128>>>(M, query, 1200);
    phaseB_k<1200, 10, 10, false, false, false, true,  false>
        <<<(BB * 1200 + 255) / 256, 256>>>(out, query);

    // --- iter 1 ---
    phaseA<120, false><<<dim3(10, BB, 2), 128>>>(M, hbase, 960);
    phaseB_k< 960, 10,  8, false, true,  true,  false, false>
        <<<(BB * 960 + 255) / 256, 256>>>(out, query);

    // --- iter 2 ---
    phaseA<120, false><<<dim3( 8, BB, 2), 128>>>(M, hbase, 720);
    phaseB_k< 720,  8,  6, true,  true,  false, false, false>
        <<<(BB * 720 + 255) / 256, 256>>>(out, query);

    // --- iter 3 ---
    phaseA< 60, false><<<dim3(12, BB, 1), 128>>>(M, hbase, 480);
    phaseB_k< 480, 12,  8, true,  true,  false, false, false>
        <<<(BB * 480 + 255) / 256, 256>>>(out, query);

    // --- iter 4 ---
    phaseA< 60, false><<<dim3( 8, BB, 1),  64>>>(M, hbase, 240);
    phaseB_k< 240,  8,  4, true,  false, false, false, true >
        <<<(NPB + 255) / 256, 256>>>(out, query);
}